// round 5
// baseline (speedup 1.0000x reference)
#include <cuda_runtime.h>
#include <cuda_fp16.h>
#include <stdint.h>

// GraphMatcher power iteration, GB300/sm_100a.
// K stored once as u8 = round(255*K^2) (squared domain doubles precision at the
// large-K winners; sqrt per message restores). Per-graph CTA holds 128 edges'
// K rows permanently in REGISTERS (64 regs/thread) across all 20 iterations;
// the remaining 160 edges (160 KB) stream via LDG and stay L1-resident
// (SMEM is only 47 KB -> ~181 KB L1 carveout).
// Inner loop is fp16x2 SIMD: PRMT builds half2(1024+v), HFMA2 cancels the 1024,
// HMAX2 reduces; one sqrt.approx per message.

#define BSZ      128
#define NV       32
#define EPG      256
#define EDGES_G  (EPG + NV)          // 288
#define E_RAND   (BSZ * EPG)         // 32768
#define E_TOT    (E_RAND + BSZ * NV) // 36864
#define NN       (NV * NV)           // 1024
#define ITERS    20
#define THREADS  512
#define WARPS    16
#define EPW      (EDGES_G / WARPS)   // 18 edges per warp (contiguous chunk)
#define NREG     8                   // edges held in registers per warp
#define NSTR     (EPW - NREG)        // 10 streamed edges per warp

// 37.75 MB u8 scratch for quantized K^2
__device__ uint8_t g_K8[(size_t)E_TOT * NN];

// ---------------------------------------------------------------------------
// Quantize K (fp32 in [0,1)) -> u8 fixed point of K^2. 16 elements per thread.
// ---------------------------------------------------------------------------
__global__ void k_convert(const float* __restrict__ K) {
    size_t i = ((size_t)blockIdx.x * blockDim.x + threadIdx.x) * 16;
    if (i >= (size_t)E_TOT * NN) return;
    uint32_t w[4];
    #pragma unroll
    for (int q = 0; q < 4; q++) {
        const float4 a = *(const float4*)(K + i + q * 4);
        uint32_t b0 = __float2uint_rn(a.x * a.x * 255.f);
        uint32_t b1 = __float2uint_rn(a.y * a.y * 255.f);
        uint32_t b2 = __float2uint_rn(a.z * a.z * 255.f);
        uint32_t b3 = __float2uint_rn(a.w * a.w * 255.f);
        w[q] = b0 | (b1 << 8) | (b2 << 16) | (b3 << 24);
    }
    *(uint4*)(g_K8 + i) = make_uint4(w[0], w[1], w[2], w[3]);
}

// ---------------------------------------------------------------------------
// Block-wide sum over 512 threads.
// ---------------------------------------------------------------------------
__device__ __forceinline__ float block_sum512(float v, float* red, int tid) {
    #pragma unroll
    for (int o = 16; o > 0; o >>= 1) v += __shfl_down_sync(0xFFFFFFFFu, v, o);
    if ((tid & 31) == 0) red[tid >> 5] = v;
    __syncthreads();
    if (tid < 32) {
        float w = (tid < WARPS) ? red[tid] : 0.f;
        #pragma unroll
        for (int o = 8; o > 0; o >>= 1) w += __shfl_down_sync(0xFFFFFFFFu, w, o);
        if (tid == 0) red[0] = w;
    }
    __syncthreads();
    float r = red[0];
    __syncthreads();
    return r;
}

// Global K row index for per-graph edge k (random edges then self loops).
__device__ __forceinline__ int krow(int g, int k) {
    return (k < EPG) ? (g * EPG + k) : (E_RAND + g * NV + (k - EPG));
}

// 4 u8 K-values vs one uint4 of packed x^2 data (X01,Y01,X23,Y23 as half2 bits).
// h = 1024+v exactly (bits 0x6400|v); hfma2(h, X, -1024*X) = v*X, one rounding.
__device__ __forceinline__ void quad_op(uint32_t kw, uint4 xv,
                                        __half2& ma, __half2& mb) {
    uint32_t h01u = __byte_perm(kw, 0x64646464u, 0x4140);
    uint32_t h23u = __byte_perm(kw, 0x64646464u, 0x4342);
    __half2 h01 = *reinterpret_cast<__half2*>(&h01u);
    __half2 h23 = *reinterpret_cast<__half2*>(&h23u);
    __half2 X01 = *reinterpret_cast<__half2*>(&xv.x);
    __half2 Y01 = *reinterpret_cast<__half2*>(&xv.y);
    __half2 X23 = *reinterpret_cast<__half2*>(&xv.z);
    __half2 Y23 = *reinterpret_cast<__half2*>(&xv.w);
    ma = __hmax2(ma, __hfma2(h01, X01, Y01));
    mb = __hmax2(mb, __hfma2(h23, X23, Y23));
}

// Compute one edge's messages from its two K quad-words and write to msgs.
__device__ __forceinline__ void edge_compute(int k, uint4 q0, uint4 q1,
                                             const uint4* __restrict__ xq,
                                             const uint16_t* __restrict__ edst,
                                             float* __restrict__ msgs, int lane) {
    const uint4* xd = xq + (int)edst[k] * 8;
    __half2 ma = __float2half2_rn(0.f), mb = ma;
    quad_op(q0.x, xd[0], ma, mb);
    quad_op(q0.y, xd[1], ma, mb);
    quad_op(q0.z, xd[2], ma, mb);
    quad_op(q0.w, xd[3], ma, mb);
    quad_op(q1.x, xd[4], ma, mb);
    quad_op(q1.y, xd[5], ma, mb);
    quad_op(q1.z, xd[6], ma, mb);
    quad_op(q1.w, xd[7], ma, mb);
    __half2 m2 = __hmax2(ma, mb);
    float m2f = __half2float(__hmax(__low2half(m2), __high2half(m2)));
    float msg;
    asm("sqrt.approx.f32 %0, %1;" : "=f"(msg) : "f"(m2f));
    msgs[k * NV + lane] = msg;
}

// ---------------------------------------------------------------------------
// SMEM layout (bytes):
//   msgs   [0      ..  36864)  288*32 fp32
//   xq     [36864  ..  40960)  32 nodes * 8 quad-uint4 (packed x^2 half2)
//   outv   [40960  ..  45056)  1024 fp32 (unnormalized x)
//   esrc   [45056  ..  45632)  288 u16
//   edst   [45632  ..  46208)  288 u16
//   glist  [46208  ..  46784)  288 u16
//   goff   [46784  ..  46916)  33 int
//   red    [46916  ..  47044)  32 fp32
// ---------------------------------------------------------------------------
#define SMEM_BYTES 47044

__global__ __launch_bounds__(THREADS, 1) void k_mpm(
    const void* __restrict__ ei_raw,
    const float* __restrict__ x_in,
    float* __restrict__ out)
{
    extern __shared__ char sm[];
    float*    msgs   = (float*)sm;
    uint4*    xq     = (uint4*)(sm + 36864);
    float*    outv   = (float*)(sm + 40960);
    uint16_t* esrc   = (uint16_t*)(sm + 45056);
    uint16_t* edst   = (uint16_t*)(sm + 45632);
    uint16_t* glist  = (uint16_t*)(sm + 46208);
    int*      goff   = (int*)(sm + 46784);
    float*    red    = (float*)(sm + 46916);

    const int tid  = threadIdx.x;
    const int g    = blockIdx.x;
    const int wid  = tid >> 5, lane = tid & 31;

    // ---- int32/int64 detection (warp 0, broadcast through red[1]) ----
    if (tid < 32) {
        unsigned long long v = ((const unsigned long long*)ei_raw)[1 + (lane & 15)];
        unsigned bal = __ballot_sync(0xFFFFFFFFu, v < 4096ull);
        if (lane == 0) red[1] = (bal == 0xFFFFFFFFu) ? 1.0f : 0.0f;
    }
    __syncthreads();
    const int is64 = (red[1] != 0.0f);

    // ---- per-graph edge tables ----
    for (int k = tid; k < EDGES_G; k += THREADS) {
        int e = krow(g, k);
        long long s, d;
        if (is64) {
            const long long* p = (const long long*)ei_raw;
            s = p[e]; d = p[E_TOT + e];
        } else {
            const int* p = (const int*)ei_raw;
            s = p[e]; d = p[E_TOT + e];
        }
        esrc[k] = (uint16_t)(s - (long long)g * NV);
        edst[k] = (uint16_t)(d - (long long)g * NV);
    }
    __syncthreads();

    // per-src gather lists (serial on thread 0; once per launch, tiny)
    if (tid == 0) {
        int cnt[NV];
        #pragma unroll
        for (int s = 0; s < NV; s++) cnt[s] = 0;
        for (int k = 0; k < EDGES_G; k++) cnt[esrc[k]]++;
        int off = 0;
        for (int s = 0; s < NV; s++) { goff[s] = off; off += cnt[s]; cnt[s] = goff[s]; }
        goff[NV] = off;
        for (int k = 0; k < EDGES_G; k++) { int s = esrc[k]; glist[cnt[s]++] = (uint16_t)k; }
    }

    // ---- preload this warp's register-resident K rows (edges kbase..kbase+7) ----
    const int kbase = wid * EPW;
    uint4 kreg[NREG][2];
    #pragma unroll
    for (int s = 0; s < NREG; s++) {
        const uint4* p = (const uint4*)(g_K8 + (size_t)krow(g, kbase + s) * NN) + lane * 2;
        kreg[s][0] = p[0];
        kreg[s][1] = p[1];
    }

    // ---- x0: load raw x, get norm ----
    float ss = 0.f;
    for (int t = tid; t < NN; t += THREADS) {
        float v = x_in[(size_t)g * NN + t];
        outv[t] = v;
        ss += v * v;
    }
    float inv = rsqrtf(block_sum512(ss, red, tid));

    const __half2 NEG1024 = __float2half2_rn(-1024.f);

    for (int it = 0; it < ITERS; it++) {
        // ---- pack x^2 as half2 quads: xq[node*8+q] = (X01,Y01,X23,Y23) ----
        if (tid < NV * 8) {
            int node = tid >> 3, q = tid & 7, j0 = q * 4;
            const float* xr = outv + node * NV + j0;
            float v0 = xr[0] * inv, v1 = xr[1] * inv, v2 = xr[2] * inv, v3 = xr[3] * inv;
            __half2 Xa = __floats2half2_rn(v0 * v0, v1 * v1);
            __half2 Xb = __floats2half2_rn(v2 * v2, v3 * v3);
            __half2 Ya = __hmul2(Xa, NEG1024);   // exact (power of two)
            __half2 Yb = __hmul2(Xb, NEG1024);
            uint4 w;
            w.x = *reinterpret_cast<uint32_t*>(&Xa);
            w.y = *reinterpret_cast<uint32_t*>(&Ya);
            w.z = *reinterpret_cast<uint32_t*>(&Xb);
            w.w = *reinterpret_cast<uint32_t*>(&Yb);
            xq[tid] = w;
        }
        __syncthreads();

        // ---- phase 1: per-edge messages. warp<->edge chunk, lane<->row i ----
        // msg[e][i] = sqrt(max_j x2[dst][j] * K2[e][i][j])   (scale-free)

        // hoist first two streamed prefetches (covered by register-edge compute)
        uint4 b0[2], b1[2];
        {
            const uint4* p0 = (const uint4*)(g_K8 + (size_t)krow(g, kbase + NREG) * NN) + lane * 2;
            b0[0] = p0[0]; b0[1] = p0[1];
            const uint4* p1 = (const uint4*)(g_K8 + (size_t)krow(g, kbase + NREG + 1) * NN) + lane * 2;
            b1[0] = p1[0]; b1[1] = p1[1];
        }

        // register-resident edges: zero K loads
        #pragma unroll
        for (int s = 0; s < NREG; s++)
            edge_compute(kbase + s, kreg[s][0], kreg[s][1], xq, edst, msgs, lane);

        // streamed edges (L1-resident after iter 1): depth-2 register prefetch
        #pragma unroll
        for (int s = 0; s < NSTR; s++) {
            int k = kbase + NREG + s;
            uint4 q0, q1;
            if (s & 1) { q0 = b1[0]; q1 = b1[1]; }
            else       { q0 = b0[0]; q1 = b0[1]; }
            if (s + 2 < NSTR) {
                const uint4* pn = (const uint4*)(g_K8 + (size_t)krow(g, k + 2) * NN) + lane * 2;
                if (s & 1) { b1[0] = pn[0]; b1[1] = pn[1]; }
                else       { b0[0] = pn[0]; b0[1] = pn[1]; }
            }
            edge_compute(k, q0, q1, xq, edst, msgs, lane);
        }
        __syncthreads();

        // ---- phase 2: segment-sum over src + squared-norm partial ----
        float ss2 = 0.f;
        #pragma unroll
        for (int t = tid; t < NN; t += THREADS) {
            int s = t >> 5, i = t & 31;      // warp-uniform s -> broadcast list loads
            float a = 0.f;
            int b = goff[s], e2 = goff[s + 1];
            for (int q = b; q < e2; q++)
                a += msgs[(int)glist[q] * NV + i];
            outv[t] = a;
            ss2 += a * a;
        }
        inv = rsqrtf(block_sum512(ss2, red, tid));
        // outv stays unnormalized; inv carried in registers
    }

    // ---- output: out[g, i, s] = x[g*32+s, i]  (transpose last two dims) ----
    for (int t = tid; t < NN; t += THREADS) {
        int i = t >> 5, s = t & 31;
        out[(size_t)g * NN + t] = outv[s * NV + i] * inv;
    }
}

// ---------------------------------------------------------------------------
extern "C" void kernel_launch(void* const* d_in, const int* in_sizes, int n_in,
                              void* d_out, int out_size) {
    const float* K  = (const float*)d_in[0];
    const void*  ei = d_in[1];
    const float* x  = (const float*)d_in[2];
    float* out = (float*)d_out;

    (void)in_sizes; (void)n_in; (void)out_size;

    cudaFuncSetAttribute(k_mpm, cudaFuncAttributeMaxDynamicSharedMemorySize, SMEM_BYTES);

    // 36864*1024 elems / 16 per thread / 256 per block = 9216 blocks (exact)
    k_convert<<<9216, 256>>>(K);

    k_mpm<<<BSZ, THREADS, SMEM_BYTES>>>(ei, x, out);
}

// round 6
// speedup vs baseline: 3.0902x; 3.0902x over previous
#include <cuda_runtime.h>
#include <cuda_fp16.h>
#include <stdint.h>

// GraphMatcher power iteration, GB300/sm_100a.
// K stored once as u8 = round(255*K^2) (squared domain doubles precision at the
// large-K winners; sqrt per message restores). One CTA per graph, 1024 threads
// (32 warps -> 50% occupancy for latency hiding), 9 edges per warp, K streamed
// from L1/L2 with depth-2 register prefetch. Inner loop is fp16x2 SIMD:
// PRMT builds half2(1024+v), HFMA2 cancels the 1024, HMAX2 reduces.

#define BSZ      128
#define NV       32
#define EPG      256
#define EDGES_G  (EPG + NV)          // 288
#define E_RAND   (BSZ * EPG)         // 32768
#define E_TOT    (E_RAND + BSZ * NV) // 36864
#define NN       (NV * NV)           // 1024
#define ITERS    20
#define THREADS  1024
#define WARPS    32
#define EPW      (EDGES_G / WARPS)   // 9 edges per warp (contiguous chunk)

// 37.75 MB u8 scratch for quantized K^2
__device__ uint8_t g_K8[(size_t)E_TOT * NN];

// ---------------------------------------------------------------------------
// Quantize K (fp32 in [0,1)) -> u8 fixed point of K^2. 16 elements per thread.
// ---------------------------------------------------------------------------
__global__ void k_convert(const float* __restrict__ K) {
    size_t i = ((size_t)blockIdx.x * blockDim.x + threadIdx.x) * 16;
    if (i >= (size_t)E_TOT * NN) return;
    uint32_t w[4];
    #pragma unroll
    for (int q = 0; q < 4; q++) {
        const float4 a = *(const float4*)(K + i + q * 4);
        uint32_t b0 = __float2uint_rn(a.x * a.x * 255.f);
        uint32_t b1 = __float2uint_rn(a.y * a.y * 255.f);
        uint32_t b2 = __float2uint_rn(a.z * a.z * 255.f);
        uint32_t b3 = __float2uint_rn(a.w * a.w * 255.f);
        w[q] = b0 | (b1 << 8) | (b2 << 16) | (b3 << 24);
    }
    *(uint4*)(g_K8 + i) = make_uint4(w[0], w[1], w[2], w[3]);
}

// ---------------------------------------------------------------------------
// Block-wide sum over 1024 threads (32 warps).
// ---------------------------------------------------------------------------
__device__ __forceinline__ float block_sum1024(float v, float* red, int tid) {
    #pragma unroll
    for (int o = 16; o > 0; o >>= 1) v += __shfl_down_sync(0xFFFFFFFFu, v, o);
    if ((tid & 31) == 0) red[tid >> 5] = v;
    __syncthreads();
    if (tid < 32) {
        float w = red[tid];
        #pragma unroll
        for (int o = 16; o > 0; o >>= 1) w += __shfl_down_sync(0xFFFFFFFFu, w, o);
        if (tid == 0) red[0] = w;
    }
    __syncthreads();
    float r = red[0];
    __syncthreads();
    return r;
}

// Global K row index for per-graph edge k (random edges then self loops).
__device__ __forceinline__ int krow(int g, int k) {
    return (k < EPG) ? (g * EPG + k) : (E_RAND + g * NV + (k - EPG));
}

// 4 u8 K-values vs one uint4 of packed x^2 data (X01,Y01,X23,Y23 as half2 bits).
// h = 1024+v exactly (bits 0x6400|v); hfma2(h, X, -1024*X) = v*X, one rounding.
__device__ __forceinline__ void quad_op(uint32_t kw, uint4 xv,
                                        __half2& ma, __half2& mb) {
    uint32_t h01u = __byte_perm(kw, 0x64646464u, 0x4140);
    uint32_t h23u = __byte_perm(kw, 0x64646464u, 0x4342);
    __half2 h01 = *reinterpret_cast<__half2*>(&h01u);
    __half2 h23 = *reinterpret_cast<__half2*>(&h23u);
    __half2 X01 = *reinterpret_cast<__half2*>(&xv.x);
    __half2 Y01 = *reinterpret_cast<__half2*>(&xv.y);
    __half2 X23 = *reinterpret_cast<__half2*>(&xv.z);
    __half2 Y23 = *reinterpret_cast<__half2*>(&xv.w);
    ma = __hmax2(ma, __hfma2(h01, X01, Y01));
    mb = __hmax2(mb, __hfma2(h23, X23, Y23));
}

// Compute one edge's messages from its two K quad-words and write to msgs.
__device__ __forceinline__ void edge_compute(int k, uint4 q0, uint4 q1,
                                             const uint4* __restrict__ xq,
                                             const uint16_t* __restrict__ edst,
                                             float* __restrict__ msgs, int lane) {
    const uint4* xd = xq + (int)edst[k] * 8;
    __half2 ma = __float2half2_rn(0.f), mb = ma;
    quad_op(q0.x, xd[0], ma, mb);
    quad_op(q0.y, xd[1], ma, mb);
    quad_op(q0.z, xd[2], ma, mb);
    quad_op(q0.w, xd[3], ma, mb);
    quad_op(q1.x, xd[4], ma, mb);
    quad_op(q1.y, xd[5], ma, mb);
    quad_op(q1.z, xd[6], ma, mb);
    quad_op(q1.w, xd[7], ma, mb);
    __half2 m2 = __hmax2(ma, mb);
    float m2f = __half2float(__hmax(__low2half(m2), __high2half(m2)));
    float msg;
    asm("sqrt.approx.f32 %0, %1;" : "=f"(msg) : "f"(m2f));
    msgs[k * NV + lane] = msg;
}

// ---------------------------------------------------------------------------
// SMEM layout (bytes):
//   msgs   [0      ..  36864)  288*32 fp32
//   xq     [36864  ..  40960)  32 nodes * 8 quad-uint4 (packed x^2 half2)
//   outv   [40960  ..  45056)  1024 fp32 (unnormalized x)
//   esrc   [45056  ..  45632)  288 u16
//   edst   [45632  ..  46208)  288 u16
//   glist  [46208  ..  46784)  288 u16
//   goff   [46784  ..  46916)  33 int
//   red    [46916  ..  47044)  32 fp32
// ---------------------------------------------------------------------------
#define SMEM_BYTES 47044

__global__ __launch_bounds__(THREADS, 1) void k_mpm(
    const void* __restrict__ ei_raw,
    const float* __restrict__ x_in,
    float* __restrict__ out)
{
    extern __shared__ char sm[];
    float*    msgs   = (float*)sm;
    uint4*    xq     = (uint4*)(sm + 36864);
    float*    outv   = (float*)(sm + 40960);
    uint16_t* esrc   = (uint16_t*)(sm + 45056);
    uint16_t* edst   = (uint16_t*)(sm + 45632);
    uint16_t* glist  = (uint16_t*)(sm + 46208);
    int*      goff   = (int*)(sm + 46784);
    float*    red    = (float*)(sm + 46916);

    const int tid  = threadIdx.x;
    const int g    = blockIdx.x;
    const int wid  = tid >> 5, lane = tid & 31;

    // ---- int32/int64 detection (warp 0, broadcast through red[1]) ----
    if (tid < 32) {
        unsigned long long v = ((const unsigned long long*)ei_raw)[1 + (lane & 15)];
        unsigned bal = __ballot_sync(0xFFFFFFFFu, v < 4096ull);
        if (lane == 0) red[1] = (bal == 0xFFFFFFFFu) ? 1.0f : 0.0f;
    }
    __syncthreads();
    const int is64 = (red[1] != 0.0f);

    // ---- per-graph edge tables ----
    if (tid < EDGES_G) {
        int k = tid;
        int e = krow(g, k);
        long long s, d;
        if (is64) {
            const long long* p = (const long long*)ei_raw;
            s = p[e]; d = p[E_TOT + e];
        } else {
            const int* p = (const int*)ei_raw;
            s = p[e]; d = p[E_TOT + e];
        }
        esrc[k] = (uint16_t)(s - (long long)g * NV);
        edst[k] = (uint16_t)(d - (long long)g * NV);
    }
    __syncthreads();

    // per-src gather lists (serial on thread 0; once per launch, tiny)
    if (tid == 0) {
        int cnt[NV];
        #pragma unroll
        for (int s = 0; s < NV; s++) cnt[s] = 0;
        for (int k = 0; k < EDGES_G; k++) cnt[esrc[k]]++;
        int off = 0;
        for (int s = 0; s < NV; s++) { goff[s] = off; off += cnt[s]; cnt[s] = goff[s]; }
        goff[NV] = off;
        for (int k = 0; k < EDGES_G; k++) { int s = esrc[k]; glist[cnt[s]++] = (uint16_t)k; }
    }

    // ---- x0: load raw x, get norm (1 element per thread) ----
    float v0x = x_in[(size_t)g * NN + tid];
    outv[tid] = v0x;
    float inv = rsqrtf(block_sum1024(v0x * v0x, red, tid));

    const __half2 NEG1024 = __float2half2_rn(-1024.f);
    const int kbase = wid * EPW;

    for (int it = 0; it < ITERS; it++) {
        // ---- pack x^2 as half2 quads: xq[node*8+q] = (X01,Y01,X23,Y23) ----
        if (tid < NV * 8) {
            int node = tid >> 3, q = tid & 7, j0 = q * 4;
            const float* xr = outv + node * NV + j0;
            float v0 = xr[0] * inv, v1 = xr[1] * inv, v2 = xr[2] * inv, v3 = xr[3] * inv;
            __half2 Xa = __floats2half2_rn(v0 * v0, v1 * v1);
            __half2 Xb = __floats2half2_rn(v2 * v2, v3 * v3);
            __half2 Ya = __hmul2(Xa, NEG1024);   // exact (power of two)
            __half2 Yb = __hmul2(Xb, NEG1024);
            uint4 w;
            w.x = *reinterpret_cast<uint32_t*>(&Xa);
            w.y = *reinterpret_cast<uint32_t*>(&Ya);
            w.z = *reinterpret_cast<uint32_t*>(&Xb);
            w.w = *reinterpret_cast<uint32_t*>(&Yb);
            xq[tid] = w;
        }
        __syncthreads();

        // ---- phase 1: per-edge messages. warp<->9-edge chunk, lane<->row i ----
        // msg[e][i] = sqrt(max_j x2[dst][j] * K2[e][i][j])   (scale-free)
        {
            // depth-2 register prefetch
            uint4 b0[2], b1[2];
            {
                const uint4* p0 = (const uint4*)(g_K8 + (size_t)krow(g, kbase) * NN) + lane * 2;
                b0[0] = p0[0]; b0[1] = p0[1];
                const uint4* p1 = (const uint4*)(g_K8 + (size_t)krow(g, kbase + 1) * NN) + lane * 2;
                b1[0] = p1[0]; b1[1] = p1[1];
            }
            #pragma unroll
            for (int s = 0; s < EPW; s++) {
                int k = kbase + s;
                uint4 q0, q1;
                if (s & 1) { q0 = b1[0]; q1 = b1[1]; }
                else       { q0 = b0[0]; q1 = b0[1]; }
                if (s + 2 < EPW) {
                    const uint4* pn = (const uint4*)(g_K8 + (size_t)krow(g, k + 2) * NN) + lane * 2;
                    if (s & 1) { b1[0] = pn[0]; b1[1] = pn[1]; }
                    else       { b0[0] = pn[0]; b0[1] = pn[1]; }
                }
                edge_compute(k, q0, q1, xq, edst, msgs, lane);
            }
        }
        __syncthreads();

        // ---- phase 2: segment-sum over src + squared-norm partial ----
        // one t per thread; s warp-uniform -> broadcast list loads
        float a;
        {
            int s = tid >> 5, i = tid & 31;
            a = 0.f;
            int b = goff[s], e2 = goff[s + 1];
            for (int q = b; q < e2; q++)
                a += msgs[(int)glist[q] * NV + i];
        }
        __syncthreads();   // msgs reads done before outv overwrite? (different arrays; kept for xq/outv ordering)
        outv[tid] = a;
        inv = rsqrtf(block_sum1024(a * a, red, tid));
        // outv stays unnormalized; inv carried in registers
    }

    // ---- output: out[g, i, s] = x[g*32+s, i]  (transpose last two dims) ----
    {
        int i = tid >> 5, s = tid & 31;
        out[(size_t)g * NN + tid] = outv[s * NV + i] * inv;
    }
}

// ---------------------------------------------------------------------------
extern "C" void kernel_launch(void* const* d_in, const int* in_sizes, int n_in,
                              void* d_out, int out_size) {
    const float* K  = (const float*)d_in[0];
    const void*  ei = d_in[1];
    const float* x  = (const float*)d_in[2];
    float* out = (float*)d_out;

    (void)in_sizes; (void)n_in; (void)out_size;

    cudaFuncSetAttribute(k_mpm, cudaFuncAttributeMaxDynamicSharedMemorySize, SMEM_BYTES);

    // 36864*1024 elems / 16 per thread / 256 per block = 9216 blocks (exact)
    k_convert<<<9216, 256>>>(K);

    k_mpm<<<BSZ, THREADS, SMEM_BYTES>>>(ei, x, out);
}

// round 8
// speedup vs baseline: 3.0962x; 1.0020x over previous
#include <cuda_runtime.h>
#include <cuda_fp16.h>
#include <stdint.h>

// GraphMatcher power iteration, GB300/sm_100a.
// K stored once as u8 = round(255*K^2) (squared domain doubles precision at the
// large-K winners; sqrt per message restores). One CTA per graph, 1024 threads.
// Phase 1 processes edges in dst-sorted order (precomputed per-warp slot words)
// so the dst node's packed x^2 block stays in registers across runs of equal
// dst: ~2 xq block loads per warp per iteration instead of 9.

#define BSZ      128
#define NV       32
#define EPG      256
#define EDGES_G  (EPG + NV)          // 288
#define E_RAND   (BSZ * EPG)         // 32768
#define E_TOT    (E_RAND + BSZ * NV) // 36864
#define NN       (NV * NV)           // 1024
#define ITERS    20
#define THREADS  1024
#define WARPS    32
#define EPW      (EDGES_G / WARPS)   // 9 edges per warp

// 37.75 MB u8 scratch for quantized K^2
__device__ uint8_t g_K8[(size_t)E_TOT * NN];

// ---------------------------------------------------------------------------
// Quantize K (fp32 in [0,1)) -> u8 fixed point of K^2. 16 elements per thread.
// ---------------------------------------------------------------------------
__global__ void k_convert(const float* __restrict__ K) {
    size_t i = ((size_t)blockIdx.x * blockDim.x + threadIdx.x) * 16;
    if (i >= (size_t)E_TOT * NN) return;
    uint32_t w[4];
    #pragma unroll
    for (int q = 0; q < 4; q++) {
        const float4 a = *(const float4*)(K + i + q * 4);
        uint32_t b0 = __float2uint_rn(a.x * a.x * 255.f);
        uint32_t b1 = __float2uint_rn(a.y * a.y * 255.f);
        uint32_t b2 = __float2uint_rn(a.z * a.z * 255.f);
        uint32_t b3 = __float2uint_rn(a.w * a.w * 255.f);
        w[q] = b0 | (b1 << 8) | (b2 << 16) | (b3 << 24);
    }
    *(uint4*)(g_K8 + i) = make_uint4(w[0], w[1], w[2], w[3]);
}

// ---------------------------------------------------------------------------
// Block-wide sum over 1024 threads (32 warps).
// ---------------------------------------------------------------------------
__device__ __forceinline__ float block_sum1024(float v, float* red, int tid) {
    #pragma unroll
    for (int o = 16; o > 0; o >>= 1) v += __shfl_down_sync(0xFFFFFFFFu, v, o);
    if ((tid & 31) == 0) red[tid >> 5] = v;
    __syncthreads();
    if (tid < 32) {
        float w = red[tid];
        #pragma unroll
        for (int o = 16; o > 0; o >>= 1) w += __shfl_down_sync(0xFFFFFFFFu, w, o);
        if (tid == 0) red[0] = w;
    }
    __syncthreads();
    float r = red[0];
    __syncthreads();
    return r;
}

// Global K row index for per-graph edge k (random edges then self loops).
__device__ __forceinline__ int krow(int g, int k) {
    return (k < EPG) ? (g * EPG + k) : (E_RAND + g * NV + (k - EPG));
}

// 4 u8 K-values vs one uint4 of packed x^2 data (X01,Y01,X23,Y23 as half2 bits).
// h = 1024+v exactly (bits 0x6400|v); hfma2(h, X, -1024*X) = v*X, one rounding.
__device__ __forceinline__ void quad_op(uint32_t kw, uint4 xv,
                                        __half2& ma, __half2& mb) {
    uint32_t h01u = __byte_perm(kw, 0x64646464u, 0x4140);
    uint32_t h23u = __byte_perm(kw, 0x64646464u, 0x4342);
    __half2 h01 = *reinterpret_cast<__half2*>(&h01u);
    __half2 h23 = *reinterpret_cast<__half2*>(&h23u);
    __half2 X01 = *reinterpret_cast<__half2*>(&xv.x);
    __half2 Y01 = *reinterpret_cast<__half2*>(&xv.y);
    __half2 X23 = *reinterpret_cast<__half2*>(&xv.z);
    __half2 Y23 = *reinterpret_cast<__half2*>(&xv.w);
    ma = __hmax2(ma, __hfma2(h01, X01, Y01));
    mb = __hmax2(mb, __hfma2(h23, X23, Y23));
}

// ---------------------------------------------------------------------------
// SMEM layout (bytes):
//   msgs   [0      ..  36864)  288*32 fp32
//   xq     [36864  ..  40960)  32 nodes * 8 quad-uint4 (packed x^2 half2)
//   outv   [40960  ..  45056)  1024 fp32 (unnormalized x)
//   slots  [45056  ..  46208)  288 u32: row(0..15) | k(16..24) | d(25..29) | flag(30)
//   esrc   [46208  ..  46784)  288 u16
//   edst   [46784  ..  47360)  288 u16
//   glist  [47360  ..  47936)  288 u16
//   dsort  [47936  ..  48512)  288 u16 (scratch for dst sort)
//   goff   [48512  ..  48644)  33 int
//   red    [48644  ..  48772)  32 fp32
// ---------------------------------------------------------------------------
#define SMEM_BYTES 48772

__global__ __launch_bounds__(THREADS, 1) void k_mpm(
    const void* __restrict__ ei_raw,
    const float* __restrict__ x_in,
    float* __restrict__ out)
{
    extern __shared__ char sm[];
    float*    msgs   = (float*)sm;
    uint4*    xq     = (uint4*)(sm + 36864);
    float*    outv   = (float*)(sm + 40960);
    uint32_t* slots  = (uint32_t*)(sm + 45056);
    uint16_t* esrc   = (uint16_t*)(sm + 46208);
    uint16_t* edst   = (uint16_t*)(sm + 46784);
    uint16_t* glist  = (uint16_t*)(sm + 47360);
    uint16_t* dsort  = (uint16_t*)(sm + 47936);
    int*      goff   = (int*)(sm + 48512);
    float*    red    = (float*)(sm + 48644);

    const int tid  = threadIdx.x;
    const int g    = blockIdx.x;
    const int wid  = tid >> 5, lane = tid & 31;

    // ---- int32/int64 detection (warp 0, broadcast through red[1]) ----
    if (tid < 32) {
        unsigned long long v = ((const unsigned long long*)ei_raw)[1 + (lane & 15)];
        unsigned bal = __ballot_sync(0xFFFFFFFFu, v < 4096ull);
        if (lane == 0) red[1] = (bal == 0xFFFFFFFFu) ? 1.0f : 0.0f;
    }
    __syncthreads();
    const int is64 = (red[1] != 0.0f);

    // ---- per-graph edge tables ----
    if (tid < EDGES_G) {
        int k = tid;
        int e = krow(g, k);
        long long s, d;
        if (is64) {
            const long long* p = (const long long*)ei_raw;
            s = p[e]; d = p[E_TOT + e];
        } else {
            const int* p = (const int*)ei_raw;
            s = p[e]; d = p[E_TOT + e];
        }
        esrc[k] = (uint16_t)(s - (long long)g * NV);
        edst[k] = (uint16_t)(d - (long long)g * NV);
    }
    __syncthreads();

    // ---- build (a) per-src gather lists, (b) dst-sorted slot words ----
    if (tid == 0) {
        // (a) segment lists by src
        int cnt[NV];
        #pragma unroll
        for (int s = 0; s < NV; s++) cnt[s] = 0;
        for (int k = 0; k < EDGES_G; k++) cnt[esrc[k]]++;
        int off = 0;
        for (int s = 0; s < NV; s++) { goff[s] = off; off += cnt[s]; cnt[s] = goff[s]; }
        goff[NV] = off;
        for (int k = 0; k < EDGES_G; k++) { int s = esrc[k]; glist[cnt[s]++] = (uint16_t)k; }
    } else if (tid == 32) {
        // (b) counting sort of edges by dst (separate warp, runs concurrently)
        int dc[NV];
        #pragma unroll
        for (int d = 0; d < NV; d++) dc[d] = 0;
        for (int k = 0; k < EDGES_G; k++) dc[edst[k]]++;
        int off = 0;
        #pragma unroll
        for (int d = 0; d < NV; d++) { int c = dc[d]; dc[d] = off; off += c; }
        for (int k = 0; k < EDGES_G; k++) { int d = edst[k]; dsort[dc[d]++] = (uint16_t)k; }
        int dprev = -1;
        for (int idx = 0; idx < EDGES_G; idx++) {
            int k = dsort[idx];
            int d = edst[k];
            uint32_t flag = ((idx % EPW) == 0 || d != dprev) ? 1u : 0u;
            slots[idx] = (uint32_t)krow(g, k) | ((uint32_t)k << 16)
                       | ((uint32_t)d << 25) | (flag << 30);
            dprev = d;
        }
    }

    // ---- x0: load raw x, get norm (1 element per thread) ----
    float v0x = x_in[(size_t)g * NN + tid];
    outv[tid] = v0x;
    float inv = rsqrtf(block_sum1024(v0x * v0x, red, tid));
    // (block_sum's barriers also publish slots/glist to all warps)

    const __half2 NEG1024 = __float2half2_rn(-1024.f);
    const int sbase = wid * EPW;

    for (int it = 0; it < ITERS; it++) {
        // ---- pack x^2 as half2 quads: xq[node*8+q] = (X01,Y01,X23,Y23) ----
        if (tid < NV * 8) {
            int node = tid >> 3, q = tid & 7, j0 = q * 4;
            const float* xr = outv + node * NV + j0;
            float v0 = xr[0] * inv, v1 = xr[1] * inv, v2 = xr[2] * inv, v3 = xr[3] * inv;
            __half2 Xa = __floats2half2_rn(v0 * v0, v1 * v1);
            __half2 Xb = __floats2half2_rn(v2 * v2, v3 * v3);
            __half2 Ya = __hmul2(Xa, NEG1024);   // exact (power of two)
            __half2 Yb = __hmul2(Xb, NEG1024);
            uint4 w;
            w.x = *reinterpret_cast<uint32_t*>(&Xa);
            w.y = *reinterpret_cast<uint32_t*>(&Ya);
            w.z = *reinterpret_cast<uint32_t*>(&Xb);
            w.w = *reinterpret_cast<uint32_t*>(&Yb);
            xq[tid] = w;
        }
        __syncthreads();

        // ---- phase 1: dst-sorted edges; xd block reloaded only on dst change ----
        // msg[e][i] = sqrt(max_j x2[dst][j] * K2[e][i][j])   (scale-free)
        {
            uint4 xd0, xd1, xd2, xd3, xd4, xd5, xd6, xd7;
            #pragma unroll
            for (int s = 0; s < EPW; s++) {
                uint32_t sl = slots[sbase + s];       // broadcast LDS
                if (sl & (1u << 30)) {                // warp-uniform branch
                    const uint4* xp = xq + ((sl >> 25) & 31u) * 8;
                    xd0 = xp[0]; xd1 = xp[1]; xd2 = xp[2]; xd3 = xp[3];
                    xd4 = xp[4]; xd5 = xp[5]; xd6 = xp[6]; xd7 = xp[7];
                }
                const uint4* p = (const uint4*)(g_K8 + (size_t)(sl & 0xFFFFu) * NN) + lane * 2;
                uint4 q0 = p[0], q1 = p[1];
                __half2 ma = __float2half2_rn(0.f), mb = ma;
                quad_op(q0.x, xd0, ma, mb);
                quad_op(q0.y, xd1, ma, mb);
                quad_op(q0.z, xd2, ma, mb);
                quad_op(q0.w, xd3, ma, mb);
                quad_op(q1.x, xd4, ma, mb);
                quad_op(q1.y, xd5, ma, mb);
                quad_op(q1.z, xd6, ma, mb);
                quad_op(q1.w, xd7, ma, mb);
                __half2 m2 = __hmax2(ma, mb);
                float m2f = __half2float(__hmax(__low2half(m2), __high2half(m2)));
                float msg;
                asm("sqrt.approx.f32 %0, %1;" : "=f"(msg) : "f"(m2f));
                msgs[((sl >> 16) & 0x1FFu) * NV + lane] = msg;
            }
        }
        __syncthreads();

        // ---- phase 2: segment-sum over src + squared-norm ----
        float a;
        {
            int s = tid >> 5, i = tid & 31;      // s warp-uniform -> broadcast list loads
            a = 0.f;
            int b = goff[s], e2 = goff[s + 1];
            for (int q = b; q < e2; q++)
                a += msgs[(int)glist[q] * NV + i];
        }
        outv[tid] = a;
        inv = rsqrtf(block_sum1024(a * a, red, tid));
        // outv stays unnormalized; inv carried in registers
    }

    // ---- output: out[g, i, s] = x[g*32+s, i]  (transpose last two dims) ----
    {
        int i = tid >> 5, s = tid & 31;
        out[(size_t)g * NN + tid] = outv[s * NV + i] * inv;
    }
}

// ---------------------------------------------------------------------------
extern "C" void kernel_launch(void* const* d_in, const int* in_sizes, int n_in,
                              void* d_out, int out_size) {
    const float* K  = (const float*)d_in[0];
    const void*  ei = d_in[1];
    const float* x  = (const float*)d_in[2];
    float* out = (float*)d_out;

    (void)in_sizes; (void)n_in; (void)out_size;

    cudaFuncSetAttribute(k_mpm, cudaFuncAttributeMaxDynamicSharedMemorySize, SMEM_BYTES);

    // 36864*1024 elems / 16 per thread / 256 per block = 9216 blocks (exact)
    k_convert<<<9216, 256>>>(K);

    k_mpm<<<BSZ, THREADS, SMEM_BYTES>>>(ei, x, out);
}